// round 13
// baseline (speedup 1.0000x reference)
#include <cuda_runtime.h>

typedef unsigned long long u64;

#define NMAX 500000
#define EMAX 1000000
#define GMAX 5000
#define NWORDS ((NMAX + 31) / 32)

// ---- persistent scratch ----
__device__ unsigned g_tbits[NWORDS];             // target-node bitmask (fallback path)
__device__ unsigned g_sbits[NWORDS];             // S1 bitmask (targets + L2 srcs)
__device__ int    g_idx1[NMAX];                  // node -> compact S1 index
__device__ int    g_s1nodes[NMAX];               // compact S1 index -> node
__device__ int    g_cnt1[3 * NMAX];              // [p*3+r] in-edge count (layer1)
__device__ int    g_cnt2[3 * GMAX];              // [g*3+r] in-edge count at targets
__device__ float  g_agg1[(size_t)NMAX * 96];     // [(p*3+r)*32] raw h0 sums
__device__ float  g_agg2[GMAX * 192];            // [(g*3+r)*64] raw h1 sums
__device__ float4 g_h1[(size_t)NMAX * 16];       // [p][64] relu'd layer-1 output
__device__ int2   g_L1[EMAX];                    // (src, p*3+r)
__device__ int2   g_L2[EMAX];                    // (src, g*3+r)
__device__ int    g_ctr[8];                      // 0=L2 count, 1=S1 count, 2=L1 count
__device__ int    g_bad_flag;                    // ptr non-uniform? sticky, deterministic
__device__ __align__(16) float g_h0tab[256 * 32];// h0 for all 256 (shape,color) combos

// ---- packed f32x2 helpers ----
__device__ __forceinline__ u64 pack2(float x, float y) {
    u64 d;
    asm("mov.b64 %0, {%1, %2};" : "=l"(d) : "r"(__float_as_uint(x)), "r"(__float_as_uint(y)));
    return d;
}
__device__ __forceinline__ void unpack2(u64 v, float& x, float& y) {
    unsigned a, b;
    asm("mov.b64 {%0, %1}, %2;" : "=r"(a), "=r"(b) : "l"(v));
    x = __uint_as_float(a); y = __uint_as_float(b);
}
__device__ __forceinline__ u64 fma2(u64 a, u64 b, u64 c) {
    u64 d;
    asm("fma.rn.f32x2 %0, %1, %2, %3;" : "=l"(d) : "l"(a), "l"(b), "l"(c));
    return d;
}
__device__ __forceinline__ void red4(float* p, float a, float b, float c, float d) {
    asm volatile("red.global.add.v4.f32 [%0], {%1, %2, %3, %4};"
                 :: "l"(p), "f"(a), "f"(b), "f"(c), "f"(d) : "memory");
}

// ---- count-based warp claim: thread claims c slots, ONE atomic per warp ----
__device__ __forceinline__ int warp_claim_n(int* ctr, int c) {
    int lane = threadIdx.x & 31;
    int inc = c;
#pragma unroll
    for (int off = 1; off < 32; off <<= 1) {
        int v = __shfl_up_sync(0xffffffffu, inc, off);
        if (lane >= off) inc += v;
    }
    int tot = __shfl_sync(0xffffffffu, inc, 31);
    int base = 0;
    if (lane == 31 && tot > 0) base = atomicAdd(ctr, tot);
    base = __shfl_sync(0xffffffffu, base, 31);
    return base + inc - c;
}

// ---- init: h0 table (block 0); uniformity probe; target bitmask; clears ----
__global__ __launch_bounds__(256) void k_init(
    const int* __restrict__ ptr,
    const float* __restrict__ se, const float* __restrict__ ce,
    const float* __restrict__ pw, const float* __restrict__ pb,
    int n, int G)
{
    int gid = blockIdx.x * 256 + threadIdx.x;
    int total = gridDim.x * 256;
    int nw = (n + 31) / 32;

    // block 0: build the 256-entry h0 table (one combo per thread)
    if (blockIdx.x == 0) {
        int t = threadIdx.x;
        int x0 = t >> 4, x1 = t & 15;
        float v[16];
#pragma unroll
        for (int i = 0; i < 8; i++) v[i] = __ldg(&se[x0 * 8 + i]);
#pragma unroll
        for (int i = 0; i < 8; i++) v[8 + i] = __ldg(&ce[x1 * 8 + i]);
        float m[32];
#pragma unroll
        for (int j = 0; j < 32; j++) m[j] = __ldg(&pb[j]);
#pragma unroll
        for (int k = 0; k < 16; k++) {
            float vk = v[k];
#pragma unroll
            for (int j = 0; j < 32; j++) m[j] = fmaf(vk, __ldg(&pw[k * 32 + j]), m[j]);
        }
        float4* dst = (float4*)(g_h0tab + t * 32);
#pragma unroll
        for (int j = 0; j < 8; j++) {
            float4 w;
            w.x = fmaxf(m[4 * j],     0.f);
            w.y = fmaxf(m[4 * j + 1], 0.f);
            w.z = fmaxf(m[4 * j + 2], 0.f);
            w.w = fmaxf(m[4 * j + 3], 0.f);
            dst[j] = w;
        }
    }

    int s0 = __ldg(&ptr[1]) - __ldg(&ptr[0]);
    for (int g = gid; g < G; g += total) {
        bool bad = (__ldg(&ptr[g + 1]) - __ldg(&ptr[g]) != s0);
        if (g == 0) bad |= (__ldg(&ptr[0]) != 0) | (s0 <= 0);
        if (bad) atomicOr(&g_bad_flag, 1);
    }

    for (int w = gid; w < nw; w += total) {
        int base = w * 32;
        int lo = 0, hi = G;
        while (lo < hi) {
            int mid = (lo + hi) >> 1;
            if (__ldg(&ptr[mid + 1]) < base + 1) lo = mid + 1; else hi = mid;
        }
        unsigned bits = 0;
        int g = lo;
        while (g < G) {
            int t = __ldg(&ptr[g + 1]) - 1;
            if (t >= base + 32) break;
            if (t >= base && t < n) bits |= 1u << (t - base);
            g++;
        }
        g_tbits[w] = bits;
        g_sbits[w] = bits;
    }
    int m2 = 3 * G * 64 / 4;
    float4 z = make_float4(0.f, 0.f, 0.f, 0.f);
    for (int j = gid; j < m2; j += total) ((float4*)g_agg2)[j] = z;
    for (int j = gid; j < 3 * G; j += total) g_cnt2[j] = 0;
    if (gid < 8) g_ctr[gid] = 0;
}

// ---- pass A: 8 edges/thread; arithmetic fast path when ptr uniform ----
__global__ __launch_bounds__(256) void k_passA(
    const int* __restrict__ ei, const int* __restrict__ et,
    const int* __restrict__ ptr, int E, int G)
{
    // prologue reads only the harness input `ptr`
    unsigned s = (unsigned)(__ldg(&ptr[1]) - __ldg(&ptr[0]));
    int t8 = (blockIdx.x * 256 + threadIdx.x) * 8;

    cudaGridDependencySynchronize();     // before g_bad_flag / g_tbits
    bool uni = (g_bad_flag == 0);

    int d[8]; bool hit[8];
    if (t8 + 7 < E) {
        int4 v0 = *(const int4*)(ei + E + t8);
        int4 v1 = *(const int4*)(ei + E + t8 + 4);
        d[0] = v0.x; d[1] = v0.y; d[2] = v0.z; d[3] = v0.w;
        d[4] = v1.x; d[5] = v1.y; d[6] = v1.z; d[7] = v1.w;
        if (uni) {
#pragma unroll
            for (int j = 0; j < 8; j++) hit[j] = ((unsigned)d[j] % s) == s - 1;
        } else {
#pragma unroll
            for (int j = 0; j < 8; j++)
                hit[j] = (__ldg(&g_tbits[d[j] >> 5]) >> (d[j] & 31)) & 1;
        }
    } else {
#pragma unroll
        for (int j = 0; j < 8; j++) {
            hit[j] = false;
            if (t8 + j < E) {
                d[j] = __ldg(&ei[E + t8 + j]);
                hit[j] = uni ? (((unsigned)d[j] % s) == s - 1)
                             : ((__ldg(&g_tbits[d[j] >> 5]) >> (d[j] & 31)) & 1);
            }
        }
    }
    int c = 0;
#pragma unroll
    for (int j = 0; j < 8; j++) c += (int)hit[j];
    int pos = warp_claim_n(&g_ctr[0], c);
#pragma unroll
    for (int j = 0; j < 8; j++) {
        if (hit[j]) {
            int e = t8 + j;
            int dj = d[j];
            int rank;
            if (uni) rank = (int)((unsigned)dj / s);
            else {
                int lo = 0, hi = G - 1;
                while (lo < hi) {
                    int mid = (lo + hi + 1) >> 1;
                    if (__ldg(&ptr[mid]) <= dj) lo = mid; else hi = mid - 1;
                }
                rank = lo;
            }
            int r = __ldg(&et[e]);
            int sE = __ldg(&ei[e]);
            int code = rank * 3 + r;
            g_L2[pos++] = make_int2(sE, code);
            atomicAdd(&g_cnt2[code], 1);
            atomicOr(&g_sbits[sE >> 5], 1u << (sE & 31));
        }
    }
}

// ---- compact S1 from bitmask (1 word / thread, warp-scan claim) ----
__global__ __launch_bounds__(256) void k_compact(int nw) {
    int w = blockIdx.x * 256 + threadIdx.x;
    cudaGridDependencySynchronize();     // before g_sbits
    unsigned bits = (w < nw) ? g_sbits[w] : 0u;
    int p = warp_claim_n(&g_ctr[1], __popc(bits));
    float4 z = make_float4(0.f, 0.f, 0.f, 0.f);
    while (bits) {
        int b = __ffs(bits) - 1;
        bits &= bits - 1;
        int node = w * 32 + b;
        g_idx1[node] = p;
        g_s1nodes[p] = node;
        g_cnt1[p * 3] = 0; g_cnt1[p * 3 + 1] = 0; g_cnt1[p * 3 + 2] = 0;
        float4* a = (float4*)(g_agg1 + (size_t)p * 96);
#pragma unroll
        for (int k = 0; k < 24; k++) a[k] = z;
        p++;
    }
}

// ---- pass B: 8 edges/thread, single warp claim; hits -> L1 list ----
__global__ __launch_bounds__(256) void k_passB(
    const int* __restrict__ ei, const int* __restrict__ et, int E)
{
    int t8 = (blockIdx.x * 256 + threadIdx.x) * 8;
    int d[8]; bool hit[8];
    // dst loads are harness inputs — issue them before the dependency sync
    int4 v0, v1; bool full = (t8 + 7 < E);
    if (full) {
        v0 = *(const int4*)(ei + E + t8);
        v1 = *(const int4*)(ei + E + t8 + 4);
    }
    cudaGridDependencySynchronize();     // before g_sbits / g_idx1
    if (full) {
        d[0] = v0.x; d[1] = v0.y; d[2] = v0.z; d[3] = v0.w;
        d[4] = v1.x; d[5] = v1.y; d[6] = v1.z; d[7] = v1.w;
#pragma unroll
        for (int j = 0; j < 8; j++)
            hit[j] = (__ldg(&g_sbits[d[j] >> 5]) >> (d[j] & 31)) & 1;
    } else {
#pragma unroll
        for (int j = 0; j < 8; j++) {
            hit[j] = false;
            if (t8 + j < E) {
                d[j] = __ldg(&ei[E + t8 + j]);
                hit[j] = (__ldg(&g_sbits[d[j] >> 5]) >> (d[j] & 31)) & 1;
            }
        }
    }
    int c = 0;
#pragma unroll
    for (int j = 0; j < 8; j++) c += (int)hit[j];
    int pos = warp_claim_n(&g_ctr[2], c);
#pragma unroll
    for (int j = 0; j < 8; j++) {
        if (hit[j]) {
            int e = t8 + j;
            int p = __ldg(&g_idx1[d[j]]);
            int r = __ldg(&et[e]);
            int s = __ldg(&ei[e]);
            int code = p * 3 + r;
            g_L1[pos++] = make_int2(s, code);
            atomicAdd(&g_cnt1[code], 1);
        }
    }
}

// ---- layer-1 aggregation: table-lookup h0[src], scatter into agg1 ----
__global__ __launch_bounds__(256) void k_h1agg(const int* __restrict__ x) {
    cudaGridDependencySynchronize();
    int cnt = g_ctr[2];
    int stride = gridDim.x * 256;
    for (int idx = blockIdx.x * 256 + threadIdx.x; idx < cnt; idx += stride) {
        int2 e = g_L1[idx];
        int2 xv = __ldg((const int2*)x + e.x);
        const float4* hp = (const float4*)(g_h0tab + (xv.x * 16 + xv.y) * 32);
        float* dp = g_agg1 + (size_t)e.y * 32;
#pragma unroll
        for (int j = 0; j < 8; j++) {
            float4 w = __ldg(&hp[j]);
            red4(dp + 4 * j, w.x, w.y, w.z, w.w);
        }
    }
}

// ---- layer-1 transform at S1 nodes (h0 via table) ----
__global__ __launch_bounds__(256) void k_h1(
    const int* __restrict__ x,
    const float* __restrict__ w1rel, const float* __restrict__ w1root,
    const float* __restrict__ b1)
{
    __shared__ __align__(16) float s_root[2048];
    __shared__ __align__(16) float s_rel[6144];
    __shared__ float s_b1[64];
    int t = threadIdx.x;
    for (int j = t; j < 2048; j += 256) s_root[j] = w1root[j];
    for (int j = t; j < 6144; j += 256) s_rel[j] = w1rel[j];
    if (t < 64) s_b1[t] = b1[t];
    cudaGridDependencySynchronize();     // 8.2KB weight staging overlapped
    __syncthreads();

    int cnt = g_ctr[1];
    int stride = gridDim.x * 256;
    for (int p = blockIdx.x * 256 + t; p < cnt; p += stride) {
        int node = g_s1nodes[p];
        int2 xv = __ldg((const int2*)x + node);
        float h0[32];
        const float4* tp = (const float4*)(g_h0tab + (xv.x * 16 + xv.y) * 32);
#pragma unroll
        for (int j = 0; j < 8; j++) ((float4*)h0)[j] = __ldg(&tp[j]);

        u64 m[32];
#pragma unroll
        for (int j = 0; j < 32; j++) m[j] = pack2(s_b1[2 * j], s_b1[2 * j + 1]);
#pragma unroll 4
        for (int k = 0; k < 32; k++) {
            u64 hk = pack2(h0[k], h0[k]);
            const ulonglong2* row = (const ulonglong2*)(s_root + k * 64);
#pragma unroll
            for (int j = 0; j < 16; j++) {
                ulonglong2 w = row[j];
                m[2 * j]     = fma2(hk, w.x, m[2 * j]);
                m[2 * j + 1] = fma2(hk, w.y, m[2 * j + 1]);
            }
        }
        for (int r = 0; r < 3; r++) {
            int c = g_cnt1[p * 3 + r];
            if (c > 0) {
                float inv = 1.0f / (float)c;
                float a[32];
                const float4* ap = (const float4*)(g_agg1 + (size_t)(p * 3 + r) * 32);
#pragma unroll
                for (int j = 0; j < 8; j++) ((float4*)a)[j] = ap[j];
                const float* wr = s_rel + r * 2048;
#pragma unroll 4
                for (int k = 0; k < 32; k++) {
                    float av = a[k] * inv;
                    u64 hk = pack2(av, av);
                    const ulonglong2* row = (const ulonglong2*)(wr + k * 64);
#pragma unroll
                    for (int j = 0; j < 16; j++) {
                        ulonglong2 w = row[j];
                        m[2 * j]     = fma2(hk, w.x, m[2 * j]);
                        m[2 * j + 1] = fma2(hk, w.y, m[2 * j + 1]);
                    }
                }
            }
        }
        float o[64];
#pragma unroll
        for (int j = 0; j < 32; j++) unpack2(m[j], o[2 * j], o[2 * j + 1]);
        float4* hp = (float4*)(g_h1 + (size_t)p * 16);
#pragma unroll
        for (int j = 0; j < 16; j++) {
            float4 w = ((float4*)o)[j];
            w.x = fmaxf(w.x, 0.f); w.y = fmaxf(w.y, 0.f);
            w.z = fmaxf(w.z, 0.f); w.w = fmaxf(w.w, 0.f);
            hp[j] = w;
        }
    }
}

// ---- layer-2 aggregation: scatter h1[src] into agg2 ----
__global__ __launch_bounds__(256) void k_h2agg() {
    cudaGridDependencySynchronize();
    int cnt = g_ctr[0];
    int stride = gridDim.x * 256;
    for (int idx = blockIdx.x * 256 + threadIdx.x; idx < cnt; idx += stride) {
        int2 e = g_L2[idx];
        int p = __ldg(&g_idx1[e.x]);
        const float4* hp = (const float4*)(g_h1 + (size_t)p * 16);
        float* dp = g_agg2 + (size_t)e.y * 64;
#pragma unroll
        for (int j = 0; j < 16; j++) {
            float4 w = hp[j];
            red4(dp + 4 * j, w.x, w.y, w.z, w.w);
        }
    }
}

// ---- final: out[g] = relu(b2 + h1[tgt]@root + sum_r mean_r@W2_r) @ cls + cb ----
__global__ __launch_bounds__(256) void k_out(
    const int* __restrict__ ptr, const float* __restrict__ w2root,
    const float* __restrict__ b2, const float* __restrict__ w2rel,
    const float* __restrict__ cls, const float* __restrict__ cb,
    float* __restrict__ out, int G)
{
    __shared__ __align__(16) float s_w[12288];  // [3,64,64] = 48KB
    int t = threadIdx.x;
    for (int j = t; j < 12288; j += 256) s_w[j] = w2rel[j];
    cudaGridDependencySynchronize();     // 48KB weight staging overlapped
    __syncthreads();
    int g = blockIdx.x * 256 + t;
    if (g >= G) return;
    int tgt = __ldg(&ptr[g + 1]) - 1;
    int p = __ldg(&g_idx1[tgt]);

    u64 m[32];
#pragma unroll
    for (int j = 0; j < 32; j++) m[j] = pack2(__ldg(&b2[2 * j]), __ldg(&b2[2 * j + 1]));

    {   // root term: h1[tgt] @ w2_root (rows via warp-broadcast LDG)
        float h[64];
        const float4* hp = (const float4*)(g_h1 + (size_t)p * 16);
#pragma unroll
        for (int j = 0; j < 16; j++) ((float4*)h)[j] = hp[j];
#pragma unroll 4
        for (int k = 0; k < 64; k++) {
            u64 hk = pack2(h[k], h[k]);
            const ulonglong2* row = (const ulonglong2*)(w2root + k * 64);
#pragma unroll
            for (int j = 0; j < 16; j++) {
                ulonglong2 w = __ldg(&row[j]);
                m[2 * j]     = fma2(hk, w.x, m[2 * j]);
                m[2 * j + 1] = fma2(hk, w.y, m[2 * j + 1]);
            }
        }
    }
    for (int r = 0; r < 3; r++) {
        int c = g_cnt2[g * 3 + r];
        if (c > 0) {
            float inv = 1.0f / (float)c;
            float a[64];
            const float4* ap = (const float4*)(g_agg2 + (size_t)(g * 3 + r) * 64);
#pragma unroll
            for (int j = 0; j < 16; j++) ((float4*)a)[j] = ap[j];
            const float* wr = s_w + r * 4096;
#pragma unroll 4
            for (int k = 0; k < 64; k++) {
                float av = a[k] * inv;
                u64 hk = pack2(av, av);
                const ulonglong2* row = (const ulonglong2*)(wr + k * 64);
#pragma unroll
                for (int j = 0; j < 16; j++) {
                    ulonglong2 w = row[j];
                    m[2 * j]     = fma2(hk, w.x, m[2 * j]);
                    m[2 * j + 1] = fma2(hk, w.y, m[2 * j + 1]);
                }
            }
        }
    }
    float o[64];
#pragma unroll
    for (int j = 0; j < 32; j++) {
        float a, b; unpack2(m[j], a, b);
        o[2 * j] = fmaxf(a, 0.f); o[2 * j + 1] = fmaxf(b, 0.f);
    }
    float res[10];
#pragma unroll
    for (int c = 0; c < 10; c++) res[c] = __ldg(&cb[c]);
#pragma unroll 8
    for (int k = 0; k < 64; k++) {
        float hk = o[k];
#pragma unroll
        for (int c = 0; c < 10; c++) res[c] = fmaf(hk, __ldg(&cls[k * 10 + c]), res[c]);
    }
#pragma unroll
    for (int c = 0; c < 10; c++) out[(size_t)g * 10 + c] = res[c];
}

// ---- PDL launch helper: overlap launch/prologue with predecessor ----
static void launch_pdl(const void* fn, int grid, int block, void** args) {
    cudaLaunchConfig_t cfg = {};
    cfg.gridDim = dim3(grid, 1, 1);
    cfg.blockDim = dim3(block, 1, 1);
    cudaLaunchAttribute attr[1];
    attr[0].id = cudaLaunchAttributeProgrammaticStreamSerialization;
    attr[0].val.programmaticStreamSerializationAllowed = 1;
    cfg.attrs = attr;
    cfg.numAttrs = 1;
    cudaLaunchKernelExC(&cfg, fn, args);
}

extern "C" void kernel_launch(void* const* d_in, const int* in_sizes, int n_in,
                              void* d_out, int out_size)
{
    const int*   x      = (const int*)d_in[0];
    const int*   ei     = (const int*)d_in[1];
    const int*   et     = (const int*)d_in[2];
    const int*   ptr    = (const int*)d_in[3];
    const float* se     = (const float*)d_in[4];
    const float* ce     = (const float*)d_in[5];
    const float* pw     = (const float*)d_in[6];
    const float* pb     = (const float*)d_in[7];
    const float* w1rel  = (const float*)d_in[8];
    const float* w1root = (const float*)d_in[9];
    const float* b1     = (const float*)d_in[10];
    const float* w2rel  = (const float*)d_in[11];
    const float* w2root = (const float*)d_in[12];
    const float* b2     = (const float*)d_in[13];
    const float* cw     = (const float*)d_in[14];
    const float* cb     = (const float*)d_in[15];
    float* out = (float*)d_out;

    int n = in_sizes[0] / 2;       // nodes
    int E = in_sizes[1] / 2;       // edges
    int G = in_sizes[3] - 1;       // graphs
    int nw = (n + 31) / 32;

    {   // init (plain launch — first in chain)
        k_init<<<256, 256>>>(ptr, se, ce, pw, pb, n, G);
    }
    {   // passA
        void* a[] = {(void*)&ei, (void*)&et, (void*)&ptr, (void*)&E, (void*)&G};
        launch_pdl((const void*)k_passA, (E + 2047) / 2048, 256, a);
    }
    {   // compact
        void* a[] = {(void*)&nw};
        launch_pdl((const void*)k_compact, (nw + 255) / 256, 256, a);
    }
    {   // passB
        void* a[] = {(void*)&ei, (void*)&et, (void*)&E};
        launch_pdl((const void*)k_passB, (E + 2047) / 2048, 256, a);
    }
    {   // h1agg
        void* a[] = {(void*)&x};
        launch_pdl((const void*)k_h1agg, 296, 256, a);
    }
    {   // h1
        void* a[] = {(void*)&x, (void*)&w1rel, (void*)&w1root, (void*)&b1};
        launch_pdl((const void*)k_h1, 296, 256, a);
    }
    {   // h2agg
        launch_pdl((const void*)k_h2agg, 296, 256, nullptr);
    }
    {   // out
        void* a[] = {(void*)&ptr, (void*)&w2root, (void*)&b2, (void*)&w2rel,
                     (void*)&cw, (void*)&cb, (void*)&out, (void*)&G};
        launch_pdl((const void*)k_out, (G + 255) / 256, 256, a);
    }
}

// round 14
// speedup vs baseline: 1.0479x; 1.0479x over previous
#include <cuda_runtime.h>

typedef unsigned long long u64;

#define NMAX 500000
#define EMAX 1000000
#define GMAX 5000
#define NWORDS ((NMAX + 31) / 32)

// ---- persistent scratch ----
__device__ unsigned g_tbits[NWORDS];             // target-node bitmask (fallback path)
__device__ unsigned g_sbits[NWORDS];             // S1 bitmask (targets + L2 srcs)
__device__ int    g_idx1[NMAX];                  // node -> compact S1 index
__device__ int    g_s1nodes[NMAX];               // compact S1 index -> node
__device__ int    g_cnt1[3 * NMAX];              // [p*3+r] in-edge count (layer1)
__device__ int    g_cnt2[3 * GMAX];              // [g*3+r] in-edge count at targets
__device__ float  g_agg1[(size_t)NMAX * 96];     // [(p*3+r)*32] raw h0 sums
__device__ float  g_agg2[GMAX * 192];            // [(g*3+r)*64] raw h1 sums
__device__ float4 g_h1[(size_t)NMAX * 16];       // [p][64] relu'd layer-1 output
__device__ int2   g_L1[EMAX];                    // (src, p*3+r)
__device__ int2   g_L2[EMAX];                    // (src, g*3+r)
__device__ int    g_ctr[8];                      // 0=L2 count, 1=S1 count, 2=L1 count
__device__ int    g_bad_flag;                    // ptr non-uniform? sticky, deterministic

// ---- packed f32x2 helpers ----
__device__ __forceinline__ u64 pack2(float x, float y) {
    u64 d;
    asm("mov.b64 %0, {%1, %2};" : "=l"(d) : "r"(__float_as_uint(x)), "r"(__float_as_uint(y)));
    return d;
}
__device__ __forceinline__ void unpack2(u64 v, float& x, float& y) {
    unsigned a, b;
    asm("mov.b64 {%0, %1}, %2;" : "=r"(a), "=r"(b) : "l"(v));
    x = __uint_as_float(a); y = __uint_as_float(b);
}
__device__ __forceinline__ u64 fma2(u64 a, u64 b, u64 c) {
    u64 d;
    asm("fma.rn.f32x2 %0, %1, %2, %3;" : "=l"(d) : "l"(a), "l"(b), "l"(c));
    return d;
}
__device__ __forceinline__ void red4(float* p, float a, float b, float c, float d) {
    asm volatile("red.global.add.v4.f32 [%0], {%1, %2, %3, %4};"
                 :: "l"(p), "f"(a), "f"(b), "f"(c), "f"(d) : "memory");
}

// ---- count-based warp claim: thread claims c slots, ONE atomic per warp ----
__device__ __forceinline__ int warp_claim_n(int* ctr, int c) {
    int lane = threadIdx.x & 31;
    int inc = c;
#pragma unroll
    for (int off = 1; off < 32; off <<= 1) {
        int v = __shfl_up_sync(0xffffffffu, inc, off);
        if (lane >= off) inc += v;
    }
    int tot = __shfl_sync(0xffffffffu, inc, 31);
    int base = 0;
    if (lane == 31 && tot > 0) base = atomicAdd(ctr, tot);
    base = __shfl_sync(0xffffffffu, base, 31);
    return base + inc - c;
}

// ---- on-the-fly h0: emb concat -> pre layer -> relu (weights in smem) ----
__device__ __forceinline__ void compute_h0(
    int node, const int* __restrict__ x,
    const float* s_se, const float* s_ce,
    const float* s_pw, const float* s_pb, float* h)
{
    int x0 = __ldg(&x[2 * node]);
    int x1 = __ldg(&x[2 * node + 1]);
    float v[16];
    const float4* sp = (const float4*)(s_se + x0 * 8);
    const float4* cp = (const float4*)(s_ce + x1 * 8);
    ((float4*)v)[0] = sp[0]; ((float4*)v)[1] = sp[1];
    ((float4*)v)[2] = cp[0]; ((float4*)v)[3] = cp[1];

    u64 m[16];
#pragma unroll
    for (int j = 0; j < 16; j++) m[j] = pack2(s_pb[2 * j], s_pb[2 * j + 1]);
#pragma unroll
    for (int k = 0; k < 16; k++) {
        u64 hk = pack2(v[k], v[k]);
        const ulonglong2* row = (const ulonglong2*)(s_pw + k * 32);
#pragma unroll
        for (int j = 0; j < 8; j++) {
            ulonglong2 w = row[j];
            m[2 * j]     = fma2(hk, w.x, m[2 * j]);
            m[2 * j + 1] = fma2(hk, w.y, m[2 * j + 1]);
        }
    }
#pragma unroll
    for (int j = 0; j < 16; j++) {
        float a, b; unpack2(m[j], a, b);
        h[2 * j] = fmaxf(a, 0.f); h[2 * j + 1] = fmaxf(b, 0.f);
    }
}

// ---- init: uniformity probe; target bitmask; clear agg2/cnt2/ctr ----
__global__ __launch_bounds__(256) void k_init(const int* __restrict__ ptr, int n, int G) {
    int gid = blockIdx.x * 256 + threadIdx.x;
    int total = gridDim.x * 256;
    int nw = (n + 31) / 32;

    int s0 = __ldg(&ptr[1]) - __ldg(&ptr[0]);
    for (int g = gid; g < G; g += total) {
        bool bad = (__ldg(&ptr[g + 1]) - __ldg(&ptr[g]) != s0);
        if (g == 0) bad |= (__ldg(&ptr[0]) != 0) | (s0 <= 0);
        if (bad) atomicOr(&g_bad_flag, 1);
    }

    for (int w = gid; w < nw; w += total) {
        int base = w * 32;
        int lo = 0, hi = G;
        while (lo < hi) {
            int mid = (lo + hi) >> 1;
            if (__ldg(&ptr[mid + 1]) < base + 1) lo = mid + 1; else hi = mid;
        }
        unsigned bits = 0;
        int g = lo;
        while (g < G) {
            int t = __ldg(&ptr[g + 1]) - 1;
            if (t >= base + 32) break;
            if (t >= base && t < n) bits |= 1u << (t - base);
            g++;
        }
        g_tbits[w] = bits;
        g_sbits[w] = bits;
    }
    int m2 = 3 * G * 64 / 4;
    float4 z = make_float4(0.f, 0.f, 0.f, 0.f);
    for (int j = gid; j < m2; j += total) ((float4*)g_agg2)[j] = z;
    for (int j = gid; j < 3 * G; j += total) g_cnt2[j] = 0;
    if (gid < 8) g_ctr[gid] = 0;
}

// ---- pass A: 8 edges/thread; ALL heavy loads + arithmetic tests PRE-sync ----
__global__ __launch_bounds__(256) void k_passA(
    const int* __restrict__ ei, const int* __restrict__ et,
    const int* __restrict__ ptr, int E, int G)
{
    // everything below the sync reads only harness inputs -> overlaps k_init
    unsigned s = (unsigned)(__ldg(&ptr[1]) - __ldg(&ptr[0]));
    int t8 = (blockIdx.x * 256 + threadIdx.x) * 8;

    int d[8]; bool ahit[8]; int arank[8]; bool valid[8];
    if (t8 + 7 < E) {
        int4 v0 = *(const int4*)(ei + E + t8);
        int4 v1 = *(const int4*)(ei + E + t8 + 4);
        d[0] = v0.x; d[1] = v0.y; d[2] = v0.z; d[3] = v0.w;
        d[4] = v1.x; d[5] = v1.y; d[6] = v1.z; d[7] = v1.w;
#pragma unroll
        for (int j = 0; j < 8; j++) valid[j] = true;
    } else {
#pragma unroll
        for (int j = 0; j < 8; j++) {
            valid[j] = (t8 + j < E);
            d[j] = valid[j] ? __ldg(&ei[E + t8 + j]) : 0;
        }
    }
#pragma unroll
    for (int j = 0; j < 8; j++) {
        unsigned q = (unsigned)d[j] / s;
        ahit[j] = valid[j] && ((unsigned)d[j] - q * s == s - 1);
        arank[j] = (int)q;
    }

    cudaGridDependencySynchronize();     // only bad_flag/tbits + writes below
    bool uni = (g_bad_flag == 0);

    bool hit[8];
    if (uni) {
#pragma unroll
        for (int j = 0; j < 8; j++) hit[j] = ahit[j];
    } else {
#pragma unroll
        for (int j = 0; j < 8; j++)
            hit[j] = valid[j] && ((__ldg(&g_tbits[d[j] >> 5]) >> (d[j] & 31)) & 1);
    }
    int c = 0;
#pragma unroll
    for (int j = 0; j < 8; j++) c += (int)hit[j];
    int pos = warp_claim_n(&g_ctr[0], c);
#pragma unroll
    for (int j = 0; j < 8; j++) {
        if (hit[j]) {
            int e = t8 + j;
            int rank;
            if (uni) rank = arank[j];
            else {
                int dj = d[j];
                int lo = 0, hi = G - 1;
                while (lo < hi) {
                    int mid = (lo + hi + 1) >> 1;
                    if (__ldg(&ptr[mid]) <= dj) lo = mid; else hi = mid - 1;
                }
                rank = lo;
            }
            int r = __ldg(&et[e]);
            int sE = __ldg(&ei[e]);
            int code = rank * 3 + r;
            g_L2[pos++] = make_int2(sE, code);
            atomicAdd(&g_cnt2[code], 1);
            atomicOr(&g_sbits[sE >> 5], 1u << (sE & 31));
        }
    }
}

// ---- compact S1 from bitmask (1 word / thread, warp-scan claim) ----
__global__ __launch_bounds__(256) void k_compact(int nw) {
    int w = blockIdx.x * 256 + threadIdx.x;
    cudaGridDependencySynchronize();     // before g_sbits
    unsigned bits = (w < nw) ? g_sbits[w] : 0u;
    int p = warp_claim_n(&g_ctr[1], __popc(bits));
    float4 z = make_float4(0.f, 0.f, 0.f, 0.f);
    while (bits) {
        int b = __ffs(bits) - 1;
        bits &= bits - 1;
        int node = w * 32 + b;
        g_idx1[node] = p;
        g_s1nodes[p] = node;
        g_cnt1[p * 3] = 0; g_cnt1[p * 3 + 1] = 0; g_cnt1[p * 3 + 2] = 0;
        float4* a = (float4*)(g_agg1 + (size_t)p * 96);
#pragma unroll
        for (int k = 0; k < 24; k++) a[k] = z;
        p++;
    }
}

// ---- pass B: 8 edges/thread, single warp claim; hits -> L1 list ----
__global__ __launch_bounds__(256) void k_passB(
    const int* __restrict__ ei, const int* __restrict__ et, int E)
{
    int t8 = (blockIdx.x * 256 + threadIdx.x) * 8;
    int d[8]; bool hit[8];
    // dst loads are harness inputs — issue them before the dependency sync
    int4 v0, v1; bool full = (t8 + 7 < E);
    if (full) {
        v0 = *(const int4*)(ei + E + t8);
        v1 = *(const int4*)(ei + E + t8 + 4);
    }
    cudaGridDependencySynchronize();     // before g_sbits / g_idx1
    if (full) {
        d[0] = v0.x; d[1] = v0.y; d[2] = v0.z; d[3] = v0.w;
        d[4] = v1.x; d[5] = v1.y; d[6] = v1.z; d[7] = v1.w;
#pragma unroll
        for (int j = 0; j < 8; j++)
            hit[j] = (__ldg(&g_sbits[d[j] >> 5]) >> (d[j] & 31)) & 1;
    } else {
#pragma unroll
        for (int j = 0; j < 8; j++) {
            hit[j] = false;
            if (t8 + j < E) {
                d[j] = __ldg(&ei[E + t8 + j]);
                hit[j] = (__ldg(&g_sbits[d[j] >> 5]) >> (d[j] & 31)) & 1;
            }
        }
    }
    int c = 0;
#pragma unroll
    for (int j = 0; j < 8; j++) c += (int)hit[j];
    int pos = warp_claim_n(&g_ctr[2], c);
#pragma unroll
    for (int j = 0; j < 8; j++) {
        if (hit[j]) {
            int e = t8 + j;
            int p = __ldg(&g_idx1[d[j]]);
            int r = __ldg(&et[e]);
            int s = __ldg(&ei[e]);
            int code = p * 3 + r;
            g_L1[pos++] = make_int2(s, code);
            atomicAdd(&g_cnt1[code], 1);
        }
    }
}

// ---- layer-1 aggregation: scatter raw h0[src] into agg1 ----
__global__ __launch_bounds__(256) void k_h1agg(
    const int* __restrict__ x, const float* __restrict__ se, const float* __restrict__ ce,
    const float* __restrict__ pw, const float* __restrict__ pb)
{
    __shared__ __align__(16) float s_se[128], s_ce[128], s_pw[512], s_pb[32];
    int t = threadIdx.x;
    if (t < 128) { s_se[t] = se[t]; s_ce[t] = ce[t]; }
    for (int j = t; j < 512; j += 256) s_pw[j] = pw[j];
    if (t < 32) s_pb[t] = pb[t];
    cudaGridDependencySynchronize();     // prologue (input weights) overlapped
    __syncthreads();

    int cnt = g_ctr[2];
    int stride = gridDim.x * 256;
    for (int idx = blockIdx.x * 256 + t; idx < cnt; idx += stride) {
        int2 e = g_L1[idx];
        float h[32];
        compute_h0(e.x, x, s_se, s_ce, s_pw, s_pb, h);
        float* dp = g_agg1 + (size_t)e.y * 32;
#pragma unroll
        for (int j = 0; j < 8; j++)
            red4(dp + 4 * j, h[4 * j], h[4 * j + 1], h[4 * j + 2], h[4 * j + 3]);
    }
}

// ---- layer-1 transform at S1 nodes ----
__global__ __launch_bounds__(256) void k_h1(
    const int* __restrict__ x, const float* __restrict__ se, const float* __restrict__ ce,
    const float* __restrict__ pw, const float* __restrict__ pb,
    const float* __restrict__ w1rel, const float* __restrict__ w1root,
    const float* __restrict__ b1)
{
    __shared__ __align__(16) float s_se[128], s_ce[128], s_pw[512], s_pb[32];
    __shared__ __align__(16) float s_root[2048];
    __shared__ __align__(16) float s_rel[6144];
    __shared__ float s_b1[64];
    int t = threadIdx.x;
    if (t < 128) { s_se[t] = se[t]; s_ce[t] = ce[t]; }
    for (int j = t; j < 512;  j += 256) s_pw[j] = pw[j];
    for (int j = t; j < 2048; j += 256) s_root[j] = w1root[j];
    for (int j = t; j < 6144; j += 256) s_rel[j] = w1rel[j];
    if (t < 32) s_pb[t] = pb[t];
    if (t < 64) s_b1[t] = b1[t];
    cudaGridDependencySynchronize();     // 8.8KB weight staging overlapped
    __syncthreads();

    int cnt = g_ctr[1];
    int stride = gridDim.x * 256;
    for (int p = blockIdx.x * 256 + t; p < cnt; p += stride) {
        int node = g_s1nodes[p];
        float h0[32];
        compute_h0(node, x, s_se, s_ce, s_pw, s_pb, h0);

        u64 m[32];
#pragma unroll
        for (int j = 0; j < 32; j++) m[j] = pack2(s_b1[2 * j], s_b1[2 * j + 1]);
#pragma unroll 4
        for (int k = 0; k < 32; k++) {
            u64 hk = pack2(h0[k], h0[k]);
            const ulonglong2* row = (const ulonglong2*)(s_root + k * 64);
#pragma unroll
            for (int j = 0; j < 16; j++) {
                ulonglong2 w = row[j];
                m[2 * j]     = fma2(hk, w.x, m[2 * j]);
                m[2 * j + 1] = fma2(hk, w.y, m[2 * j + 1]);
            }
        }
        for (int r = 0; r < 3; r++) {
            int c = g_cnt1[p * 3 + r];
            if (c > 0) {
                float inv = 1.0f / (float)c;
                float a[32];
                const float4* ap = (const float4*)(g_agg1 + (size_t)(p * 3 + r) * 32);
#pragma unroll
                for (int j = 0; j < 8; j++) ((float4*)a)[j] = ap[j];
                const float* wr = s_rel + r * 2048;
#pragma unroll 4
                for (int k = 0; k < 32; k++) {
                    float av = a[k] * inv;
                    u64 hk = pack2(av, av);
                    const ulonglong2* row = (const ulonglong2*)(wr + k * 64);
#pragma unroll
                    for (int j = 0; j < 16; j++) {
                        ulonglong2 w = row[j];
                        m[2 * j]     = fma2(hk, w.x, m[2 * j]);
                        m[2 * j + 1] = fma2(hk, w.y, m[2 * j + 1]);
                    }
                }
            }
        }
        float o[64];
#pragma unroll
        for (int j = 0; j < 32; j++) unpack2(m[j], o[2 * j], o[2 * j + 1]);
        float4* hp = (float4*)(g_h1 + (size_t)p * 16);
#pragma unroll
        for (int j = 0; j < 16; j++) {
            float4 w = ((float4*)o)[j];
            w.x = fmaxf(w.x, 0.f); w.y = fmaxf(w.y, 0.f);
            w.z = fmaxf(w.z, 0.f); w.w = fmaxf(w.w, 0.f);
            hp[j] = w;
        }
    }
}

// ---- layer-2 aggregation: scatter h1[src] into agg2 ----
__global__ __launch_bounds__(256) void k_h2agg() {
    cudaGridDependencySynchronize();
    int cnt = g_ctr[0];
    int stride = gridDim.x * 256;
    for (int idx = blockIdx.x * 256 + threadIdx.x; idx < cnt; idx += stride) {
        int2 e = g_L2[idx];
        int p = __ldg(&g_idx1[e.x]);
        const float4* hp = (const float4*)(g_h1 + (size_t)p * 16);
        float* dp = g_agg2 + (size_t)e.y * 64;
#pragma unroll
        for (int j = 0; j < 16; j++) {
            float4 w = hp[j];
            red4(dp + 4 * j, w.x, w.y, w.z, w.w);
        }
    }
}

// ---- final: out[g] = relu(b2 + h1[tgt]@root + sum_r mean_r@W2_r) @ cls + cb ----
__global__ __launch_bounds__(256) void k_out(
    const int* __restrict__ ptr, const float* __restrict__ w2root,
    const float* __restrict__ b2, const float* __restrict__ w2rel,
    const float* __restrict__ cls, const float* __restrict__ cb,
    float* __restrict__ out, int G)
{
    __shared__ __align__(16) float s_w[12288];  // [3,64,64] = 48KB
    int t = threadIdx.x;
    for (int j = t; j < 12288; j += 256) s_w[j] = w2rel[j];
    cudaGridDependencySynchronize();     // 48KB weight staging overlapped
    __syncthreads();
    int g = blockIdx.x * 256 + t;
    if (g >= G) return;
    int tgt = __ldg(&ptr[g + 1]) - 1;
    int p = __ldg(&g_idx1[tgt]);

    u64 m[32];
#pragma unroll
    for (int j = 0; j < 32; j++) m[j] = pack2(__ldg(&b2[2 * j]), __ldg(&b2[2 * j + 1]));

    {   // root term: h1[tgt] @ w2_root (rows via warp-broadcast LDG)
        float h[64];
        const float4* hp = (const float4*)(g_h1 + (size_t)p * 16);
#pragma unroll
        for (int j = 0; j < 16; j++) ((float4*)h)[j] = hp[j];
#pragma unroll 4
        for (int k = 0; k < 64; k++) {
            u64 hk = pack2(h[k], h[k]);
            const ulonglong2* row = (const ulonglong2*)(w2root + k * 64);
#pragma unroll
            for (int j = 0; j < 16; j++) {
                ulonglong2 w = __ldg(&row[j]);
                m[2 * j]     = fma2(hk, w.x, m[2 * j]);
                m[2 * j + 1] = fma2(hk, w.y, m[2 * j + 1]);
            }
        }
    }
    for (int r = 0; r < 3; r++) {
        int c = g_cnt2[g * 3 + r];
        if (c > 0) {
            float inv = 1.0f / (float)c;
            float a[64];
            const float4* ap = (const float4*)(g_agg2 + (size_t)(g * 3 + r) * 64);
#pragma unroll
            for (int j = 0; j < 16; j++) ((float4*)a)[j] = ap[j];
            const float* wr = s_w + r * 4096;
#pragma unroll 4
            for (int k = 0; k < 64; k++) {
                float av = a[k] * inv;
                u64 hk = pack2(av, av);
                const ulonglong2* row = (const ulonglong2*)(wr + k * 64);
#pragma unroll
                for (int j = 0; j < 16; j++) {
                    ulonglong2 w = row[j];
                    m[2 * j]     = fma2(hk, w.x, m[2 * j]);
                    m[2 * j + 1] = fma2(hk, w.y, m[2 * j + 1]);
                }
            }
        }
    }
    float o[64];
#pragma unroll
    for (int j = 0; j < 32; j++) {
        float a, b; unpack2(m[j], a, b);
        o[2 * j] = fmaxf(a, 0.f); o[2 * j + 1] = fmaxf(b, 0.f);
    }
    float res[10];
#pragma unroll
    for (int c = 0; c < 10; c++) res[c] = __ldg(&cb[c]);
#pragma unroll 8
    for (int k = 0; k < 64; k++) {
        float hk = o[k];
#pragma unroll
        for (int c = 0; c < 10; c++) res[c] = fmaf(hk, __ldg(&cls[k * 10 + c]), res[c]);
    }
#pragma unroll
    for (int c = 0; c < 10; c++) out[(size_t)g * 10 + c] = res[c];
}

// ---- PDL launch helper: overlap launch/prologue with predecessor ----
static void launch_pdl(const void* fn, int grid, int block, void** args) {
    cudaLaunchConfig_t cfg = {};
    cfg.gridDim = dim3(grid, 1, 1);
    cfg.blockDim = dim3(block, 1, 1);
    cudaLaunchAttribute attr[1];
    attr[0].id = cudaLaunchAttributeProgrammaticStreamSerialization;
    attr[0].val.programmaticStreamSerializationAllowed = 1;
    cfg.attrs = attr;
    cfg.numAttrs = 1;
    cudaLaunchKernelExC(&cfg, fn, args);
}

extern "C" void kernel_launch(void* const* d_in, const int* in_sizes, int n_in,
                              void* d_out, int out_size)
{
    const int*   x      = (const int*)d_in[0];
    const int*   ei     = (const int*)d_in[1];
    const int*   et     = (const int*)d_in[2];
    const int*   ptr    = (const int*)d_in[3];
    const float* se     = (const float*)d_in[4];
    const float* ce     = (const float*)d_in[5];
    const float* pw     = (const float*)d_in[6];
    const float* pb     = (const float*)d_in[7];
    const float* w1rel  = (const float*)d_in[8];
    const float* w1root = (const float*)d_in[9];
    const float* b1     = (const float*)d_in[10];
    const float* w2rel  = (const float*)d_in[11];
    const float* w2root = (const float*)d_in[12];
    const float* b2     = (const float*)d_in[13];
    const float* cw     = (const float*)d_in[14];
    const float* cb     = (const float*)d_in[15];
    float* out = (float*)d_out;

    int n = in_sizes[0] / 2;       // nodes
    int E = in_sizes[1] / 2;       // edges
    int G = in_sizes[3] - 1;       // graphs
    int nw = (n + 31) / 32;

    k_init<<<256, 256>>>(ptr, n, G);

    {   // passA
        void* a[] = {(void*)&ei, (void*)&et, (void*)&ptr, (void*)&E, (void*)&G};
        launch_pdl((const void*)k_passA, (E + 2047) / 2048, 256, a);
    }
    {   // compact
        void* a[] = {(void*)&nw};
        launch_pdl((const void*)k_compact, (nw + 255) / 256, 256, a);
    }
    {   // passB
        void* a[] = {(void*)&ei, (void*)&et, (void*)&E};
        launch_pdl((const void*)k_passB, (E + 2047) / 2048, 256, a);
    }
    {   // h1agg
        void* a[] = {(void*)&x, (void*)&se, (void*)&ce, (void*)&pw, (void*)&pb};
        launch_pdl((const void*)k_h1agg, 296, 256, a);
    }
    {   // h1
        void* a[] = {(void*)&x, (void*)&se, (void*)&ce, (void*)&pw, (void*)&pb,
                     (void*)&w1rel, (void*)&w1root, (void*)&b1};
        launch_pdl((const void*)k_h1, 296, 256, a);
    }
    {   // h2agg
        launch_pdl((const void*)k_h2agg, 296, 256, nullptr);
    }
    {   // out
        void* a[] = {(void*)&ptr, (void*)&w2root, (void*)&b2, (void*)&w2rel,
                     (void*)&cw, (void*)&cb, (void*)&out, (void*)&G};
        launch_pdl((const void*)k_out, (G + 255) / 256, 256, a);
    }
}

// round 15
// speedup vs baseline: 1.0790x; 1.0297x over previous
#include <cuda_runtime.h>

typedef unsigned long long u64;

#define NMAX 500000
#define EMAX 1000000
#define GMAX 5000
#define NWORDS ((NMAX + 31) / 32)

// ---- persistent scratch ----
__device__ unsigned g_tbits[NWORDS];             // target-node bitmask (fallback path)
__device__ unsigned g_sbits[NWORDS];             // S1 bitmask (targets + L2 srcs)
__device__ int    g_idx1[NMAX];                  // node -> compact S1 index
__device__ int    g_s1nodes[NMAX];               // compact S1 index -> node
__device__ int    g_cnt1[3 * NMAX];              // [p*3+r] in-edge count (layer1)
__device__ int    g_cnt2[3 * GMAX];              // [g*3+r] in-edge count at targets
__device__ float  g_agg1[(size_t)NMAX * 96];     // [(p*3+r)*32] raw h0 sums
__device__ float  g_agg2[GMAX * 192];            // [(g*3+r)*64] raw h1 sums
__device__ float4 g_h1[(size_t)NMAX * 16];       // [p][64] relu'd layer-1 output
__device__ int2   g_L2[EMAX];                    // (src, g*3+r)
__device__ int    g_ctr[8];                      // 0=L2 count, 1=S1 count
__device__ int    g_bad_flag;                    // ptr non-uniform? sticky, deterministic

// ---- packed f32x2 helpers ----
__device__ __forceinline__ u64 pack2(float x, float y) {
    u64 d;
    asm("mov.b64 %0, {%1, %2};" : "=l"(d) : "r"(__float_as_uint(x)), "r"(__float_as_uint(y)));
    return d;
}
__device__ __forceinline__ void unpack2(u64 v, float& x, float& y) {
    unsigned a, b;
    asm("mov.b64 {%0, %1}, %2;" : "=r"(a), "=r"(b) : "l"(v));
    x = __uint_as_float(a); y = __uint_as_float(b);
}
__device__ __forceinline__ u64 fma2(u64 a, u64 b, u64 c) {
    u64 d;
    asm("fma.rn.f32x2 %0, %1, %2, %3;" : "=l"(d) : "l"(a), "l"(b), "l"(c));
    return d;
}
__device__ __forceinline__ void red4(float* p, float a, float b, float c, float d) {
    asm volatile("red.global.add.v4.f32 [%0], {%1, %2, %3, %4};"
                 :: "l"(p), "f"(a), "f"(b), "f"(c), "f"(d) : "memory");
}
__device__ __forceinline__ void red1(float* p, float a) {
    asm volatile("red.global.add.f32 [%0], %1;" :: "l"(p), "f"(a) : "memory");
}

// ---- count-based warp claim: thread claims c slots, ONE atomic per warp ----
__device__ __forceinline__ int warp_claim_n(int* ctr, int c) {
    int lane = threadIdx.x & 31;
    int inc = c;
#pragma unroll
    for (int off = 1; off < 32; off <<= 1) {
        int v = __shfl_up_sync(0xffffffffu, inc, off);
        if (lane >= off) inc += v;
    }
    int tot = __shfl_sync(0xffffffffu, inc, 31);
    int base = 0;
    if (lane == 31 && tot > 0) base = atomicAdd(ctr, tot);
    base = __shfl_sync(0xffffffffu, base, 31);
    return base + inc - c;
}

// ---- on-the-fly h0 (thread-serial form; used by k_h1) ----
__device__ __forceinline__ void compute_h0(
    int node, const int* __restrict__ x,
    const float* s_se, const float* s_ce,
    const float* s_pw, const float* s_pb, float* h)
{
    int x0 = __ldg(&x[2 * node]);
    int x1 = __ldg(&x[2 * node + 1]);
    float v[16];
    const float4* sp = (const float4*)(s_se + x0 * 8);
    const float4* cp = (const float4*)(s_ce + x1 * 8);
    ((float4*)v)[0] = sp[0]; ((float4*)v)[1] = sp[1];
    ((float4*)v)[2] = cp[0]; ((float4*)v)[3] = cp[1];

    u64 m[16];
#pragma unroll
    for (int j = 0; j < 16; j++) m[j] = pack2(s_pb[2 * j], s_pb[2 * j + 1]);
#pragma unroll
    for (int k = 0; k < 16; k++) {
        u64 hk = pack2(v[k], v[k]);
        const ulonglong2* row = (const ulonglong2*)(s_pw + k * 32);
#pragma unroll
        for (int j = 0; j < 8; j++) {
            ulonglong2 w = row[j];
            m[2 * j]     = fma2(hk, w.x, m[2 * j]);
            m[2 * j + 1] = fma2(hk, w.y, m[2 * j + 1]);
        }
    }
#pragma unroll
    for (int j = 0; j < 16; j++) {
        float a, b; unpack2(m[j], a, b);
        h[2 * j] = fmaxf(a, 0.f); h[2 * j + 1] = fmaxf(b, 0.f);
    }
}

// ---- init: uniformity probe; target bitmask; clear agg2/cnt2/ctr ----
__global__ __launch_bounds__(256) void k_init(const int* __restrict__ ptr, int n, int G) {
    int gid = blockIdx.x * 256 + threadIdx.x;
    int total = gridDim.x * 256;
    int nw = (n + 31) / 32;

    int s0 = __ldg(&ptr[1]) - __ldg(&ptr[0]);
    for (int g = gid; g < G; g += total) {
        bool bad = (__ldg(&ptr[g + 1]) - __ldg(&ptr[g]) != s0);
        if (g == 0) bad |= (__ldg(&ptr[0]) != 0) | (s0 <= 0);
        if (bad) atomicOr(&g_bad_flag, 1);
    }

    for (int w = gid; w < nw; w += total) {
        int base = w * 32;
        int lo = 0, hi = G;
        while (lo < hi) {
            int mid = (lo + hi) >> 1;
            if (__ldg(&ptr[mid + 1]) < base + 1) lo = mid + 1; else hi = mid;
        }
        unsigned bits = 0;
        int g = lo;
        while (g < G) {
            int t = __ldg(&ptr[g + 1]) - 1;
            if (t >= base + 32) break;
            if (t >= base && t < n) bits |= 1u << (t - base);
            g++;
        }
        g_tbits[w] = bits;
        g_sbits[w] = bits;
    }
    int m2 = 3 * G * 64 / 4;
    float4 z = make_float4(0.f, 0.f, 0.f, 0.f);
    for (int j = gid; j < m2; j += total) ((float4*)g_agg2)[j] = z;
    for (int j = gid; j < 3 * G; j += total) g_cnt2[j] = 0;
    if (gid < 8) g_ctr[gid] = 0;
}

// ---- pass A: 8 edges/thread; arithmetic fast path; loads pre-sync ----
__global__ __launch_bounds__(256) void k_passA(
    const int* __restrict__ ei, const int* __restrict__ et,
    const int* __restrict__ ptr, int E, int G)
{
    unsigned s = (unsigned)(__ldg(&ptr[1]) - __ldg(&ptr[0]));
    int t8 = (blockIdx.x * 256 + threadIdx.x) * 8;

    int d[8]; bool ahit[8]; int arank[8]; bool valid[8];
    if (t8 + 7 < E) {
        int4 v0 = *(const int4*)(ei + E + t8);
        int4 v1 = *(const int4*)(ei + E + t8 + 4);
        d[0] = v0.x; d[1] = v0.y; d[2] = v0.z; d[3] = v0.w;
        d[4] = v1.x; d[5] = v1.y; d[6] = v1.z; d[7] = v1.w;
#pragma unroll
        for (int j = 0; j < 8; j++) valid[j] = true;
    } else {
#pragma unroll
        for (int j = 0; j < 8; j++) {
            valid[j] = (t8 + j < E);
            d[j] = valid[j] ? __ldg(&ei[E + t8 + j]) : 0;
        }
    }
#pragma unroll
    for (int j = 0; j < 8; j++) {
        unsigned q = (unsigned)d[j] / s;
        ahit[j] = valid[j] && ((unsigned)d[j] - q * s == s - 1);
        arank[j] = (int)q;
    }

    cudaGridDependencySynchronize();
    bool uni = (g_bad_flag == 0);

    bool hit[8];
    if (uni) {
#pragma unroll
        for (int j = 0; j < 8; j++) hit[j] = ahit[j];
    } else {
#pragma unroll
        for (int j = 0; j < 8; j++)
            hit[j] = valid[j] && ((__ldg(&g_tbits[d[j] >> 5]) >> (d[j] & 31)) & 1);
    }
    int c = 0;
#pragma unroll
    for (int j = 0; j < 8; j++) c += (int)hit[j];
    int pos = warp_claim_n(&g_ctr[0], c);
#pragma unroll
    for (int j = 0; j < 8; j++) {
        if (hit[j]) {
            int e = t8 + j;
            int rank;
            if (uni) rank = arank[j];
            else {
                int dj = d[j];
                int lo = 0, hi = G - 1;
                while (lo < hi) {
                    int mid = (lo + hi + 1) >> 1;
                    if (__ldg(&ptr[mid]) <= dj) lo = mid; else hi = mid - 1;
                }
                rank = lo;
            }
            int r = __ldg(&et[e]);
            int sE = __ldg(&ei[e]);
            int code = rank * 3 + r;
            g_L2[pos++] = make_int2(sE, code);
            atomicAdd(&g_cnt2[code], 1);
            atomicOr(&g_sbits[sE >> 5], 1u << (sE & 31));
        }
    }
}

// ---- compact S1 from bitmask (1 word / thread, warp-scan claim) ----
__global__ __launch_bounds__(256) void k_compact(int nw) {
    int w = blockIdx.x * 256 + threadIdx.x;
    cudaGridDependencySynchronize();
    unsigned bits = (w < nw) ? g_sbits[w] : 0u;
    int p = warp_claim_n(&g_ctr[1], __popc(bits));
    float4 z = make_float4(0.f, 0.f, 0.f, 0.f);
    while (bits) {
        int b = __ffs(bits) - 1;
        bits &= bits - 1;
        int node = w * 32 + b;
        g_idx1[node] = p;
        g_s1nodes[p] = node;
        g_cnt1[p * 3] = 0; g_cnt1[p * 3 + 1] = 0; g_cnt1[p * 3 + 2] = 0;
        float4* a = (float4*)(g_agg1 + (size_t)p * 96);
#pragma unroll
        for (int k = 0; k < 24; k++) a[k] = z;
        p++;
    }
}

// ---- FUSED pass B + layer-1 aggregation ----
// phase 1: dense scan (8 edges/thread), hits -> smem buffer
// phase 2: warp-per-hit h0 compute (lane j = feature j) + coalesced red1
__global__ __launch_bounds__(256) void k_passBh1(
    const int* __restrict__ ei, const int* __restrict__ et,
    const int* __restrict__ x,
    const float* __restrict__ se, const float* __restrict__ ce,
    const float* __restrict__ pw, const float* __restrict__ pb, int E)
{
    __shared__ float s_se[128], s_ce[128];
    __shared__ int s_src[2048];
    __shared__ int s_code[2048];
    __shared__ int s_nhits;
    int t = threadIdx.x;
    int lane = t & 31;
    int wid = t >> 5;

    // prologue (harness inputs only) — overlaps predecessor via PDL
    if (t < 128) { s_se[t] = se[t]; s_ce[t] = ce[t]; }
    if (t == 0) s_nhits = 0;
    float r_pw[16];                     // pw column for this lane
#pragma unroll
    for (int k = 0; k < 16; k++) r_pw[k] = __ldg(&pw[k * 32 + lane]);
    float r_pb = __ldg(&pb[lane]);

    int t8 = (blockIdx.x * 256 + t) * 8;
    int d[8];
    int4 v0, v1; bool full = (t8 + 7 < E);
    if (full) {
        v0 = *(const int4*)(ei + E + t8);
        v1 = *(const int4*)(ei + E + t8 + 4);
    }
    __syncthreads();                    // s_nhits / weights visible

    cudaGridDependencySynchronize();    // before g_sbits / g_idx1 / g_cnt1

    bool hit[8];
    if (full) {
        d[0] = v0.x; d[1] = v0.y; d[2] = v0.z; d[3] = v0.w;
        d[4] = v1.x; d[5] = v1.y; d[6] = v1.z; d[7] = v1.w;
#pragma unroll
        for (int j = 0; j < 8; j++)
            hit[j] = (__ldg(&g_sbits[d[j] >> 5]) >> (d[j] & 31)) & 1;
    } else {
#pragma unroll
        for (int j = 0; j < 8; j++) {
            hit[j] = false;
            if (t8 + j < E) {
                d[j] = __ldg(&ei[E + t8 + j]);
                hit[j] = (__ldg(&g_sbits[d[j] >> 5]) >> (d[j] & 31)) & 1;
            }
        }
    }
#pragma unroll
    for (int j = 0; j < 8; j++) {
        if (hit[j]) {
            int e = t8 + j;
            int p = __ldg(&g_idx1[d[j]]);
            int r = __ldg(&et[e]);
            int s = __ldg(&ei[e]);
            int code = p * 3 + r;
            atomicAdd(&g_cnt1[code], 1);
            int slot = atomicAdd(&s_nhits, 1);
            s_src[slot] = s;
            s_code[slot] = code;
        }
    }
    __syncthreads();

    // phase 2: warp-cooperative dense processing of buffered hits
    int n = s_nhits;
    for (int h = wid; h < n; h += 8) {
        int src = s_src[h];
        int code = s_code[h];
        int x0 = __ldg(&x[2 * src]);        // warp-broadcast
        int x1 = __ldg(&x[2 * src + 1]);
        float acc = r_pb;
        const float* sev = s_se + x0 * 8;   // broadcast LDS
        const float* cev = s_ce + x1 * 8;
#pragma unroll
        for (int k = 0; k < 8; k++) acc = fmaf(sev[k], r_pw[k], acc);
#pragma unroll
        for (int k = 0; k < 8; k++) acc = fmaf(cev[k], r_pw[8 + k], acc);
        acc = fmaxf(acc, 0.f);
        red1(g_agg1 + (size_t)code * 32 + lane, acc);   // coalesced 32-lane scatter
    }
}

// ---- layer-1 transform at S1 nodes ----
__global__ __launch_bounds__(256) void k_h1(
    const int* __restrict__ x, const float* __restrict__ se, const float* __restrict__ ce,
    const float* __restrict__ pw, const float* __restrict__ pb,
    const float* __restrict__ w1rel, const float* __restrict__ w1root,
    const float* __restrict__ b1)
{
    __shared__ __align__(16) float s_se[128], s_ce[128], s_pw[512], s_pb[32];
    __shared__ __align__(16) float s_root[2048];
    __shared__ __align__(16) float s_rel[6144];
    __shared__ float s_b1[64];
    int t = threadIdx.x;
    if (t < 128) { s_se[t] = se[t]; s_ce[t] = ce[t]; }
    for (int j = t; j < 512;  j += 256) s_pw[j] = pw[j];
    for (int j = t; j < 2048; j += 256) s_root[j] = w1root[j];
    for (int j = t; j < 6144; j += 256) s_rel[j] = w1rel[j];
    if (t < 32) s_pb[t] = pb[t];
    if (t < 64) s_b1[t] = b1[t];
    cudaGridDependencySynchronize();
    __syncthreads();

    int cnt = g_ctr[1];
    int stride = gridDim.x * 256;
    for (int p = blockIdx.x * 256 + t; p < cnt; p += stride) {
        int node = g_s1nodes[p];
        float h0[32];
        compute_h0(node, x, s_se, s_ce, s_pw, s_pb, h0);

        u64 m[32];
#pragma unroll
        for (int j = 0; j < 32; j++) m[j] = pack2(s_b1[2 * j], s_b1[2 * j + 1]);
#pragma unroll 4
        for (int k = 0; k < 32; k++) {
            u64 hk = pack2(h0[k], h0[k]);
            const ulonglong2* row = (const ulonglong2*)(s_root + k * 64);
#pragma unroll
            for (int j = 0; j < 16; j++) {
                ulonglong2 w = row[j];
                m[2 * j]     = fma2(hk, w.x, m[2 * j]);
                m[2 * j + 1] = fma2(hk, w.y, m[2 * j + 1]);
            }
        }
        for (int r = 0; r < 3; r++) {
            int c = g_cnt1[p * 3 + r];
            if (c > 0) {
                float inv = 1.0f / (float)c;
                float a[32];
                const float4* ap = (const float4*)(g_agg1 + (size_t)(p * 3 + r) * 32);
#pragma unroll
                for (int j = 0; j < 8; j++) ((float4*)a)[j] = ap[j];
                const float* wr = s_rel + r * 2048;
#pragma unroll 4
                for (int k = 0; k < 32; k++) {
                    float av = a[k] * inv;
                    u64 hk = pack2(av, av);
                    const ulonglong2* row = (const ulonglong2*)(wr + k * 64);
#pragma unroll
                    for (int j = 0; j < 16; j++) {
                        ulonglong2 w = row[j];
                        m[2 * j]     = fma2(hk, w.x, m[2 * j]);
                        m[2 * j + 1] = fma2(hk, w.y, m[2 * j + 1]);
                    }
                }
            }
        }
        float o[64];
#pragma unroll
        for (int j = 0; j < 32; j++) unpack2(m[j], o[2 * j], o[2 * j + 1]);
        float4* hp = (float4*)(g_h1 + (size_t)p * 16);
#pragma unroll
        for (int j = 0; j < 16; j++) {
            float4 w = ((float4*)o)[j];
            w.x = fmaxf(w.x, 0.f); w.y = fmaxf(w.y, 0.f);
            w.z = fmaxf(w.z, 0.f); w.w = fmaxf(w.w, 0.f);
            hp[j] = w;
        }
    }
}

// ---- layer-2 aggregation: scatter h1[src] into agg2 ----
__global__ __launch_bounds__(256) void k_h2agg() {
    cudaGridDependencySynchronize();
    int cnt = g_ctr[0];
    int stride = gridDim.x * 256;
    for (int idx = blockIdx.x * 256 + threadIdx.x; idx < cnt; idx += stride) {
        int2 e = g_L2[idx];
        int p = __ldg(&g_idx1[e.x]);
        const float4* hp = (const float4*)(g_h1 + (size_t)p * 16);
        float* dp = g_agg2 + (size_t)e.y * 64;
#pragma unroll
        for (int j = 0; j < 16; j++) {
            float4 w = hp[j];
            red4(dp + 4 * j, w.x, w.y, w.z, w.w);
        }
    }
}

// ---- final: out[g] = relu(b2 + h1[tgt]@root + sum_r mean_r@W2_r) @ cls + cb ----
__global__ __launch_bounds__(256) void k_out(
    const int* __restrict__ ptr, const float* __restrict__ w2root,
    const float* __restrict__ b2, const float* __restrict__ w2rel,
    const float* __restrict__ cls, const float* __restrict__ cb,
    float* __restrict__ out, int G)
{
    __shared__ __align__(16) float s_w[12288];  // [3,64,64] = 48KB
    int t = threadIdx.x;
    for (int j = t; j < 12288; j += 256) s_w[j] = w2rel[j];
    cudaGridDependencySynchronize();
    __syncthreads();
    int g = blockIdx.x * 256 + t;
    if (g >= G) return;
    int tgt = __ldg(&ptr[g + 1]) - 1;
    int p = __ldg(&g_idx1[tgt]);

    u64 m[32];
#pragma unroll
    for (int j = 0; j < 32; j++) m[j] = pack2(__ldg(&b2[2 * j]), __ldg(&b2[2 * j + 1]));

    {   // root term: h1[tgt] @ w2_root (rows via warp-broadcast LDG)
        float h[64];
        const float4* hp = (const float4*)(g_h1 + (size_t)p * 16);
#pragma unroll
        for (int j = 0; j < 16; j++) ((float4*)h)[j] = hp[j];
#pragma unroll 4
        for (int k = 0; k < 64; k++) {
            u64 hk = pack2(h[k], h[k]);
            const ulonglong2* row = (const ulonglong2*)(w2root + k * 64);
#pragma unroll
            for (int j = 0; j < 16; j++) {
                ulonglong2 w = __ldg(&row[j]);
                m[2 * j]     = fma2(hk, w.x, m[2 * j]);
                m[2 * j + 1] = fma2(hk, w.y, m[2 * j + 1]);
            }
        }
    }
    for (int r = 0; r < 3; r++) {
        int c = g_cnt2[g * 3 + r];
        if (c > 0) {
            float inv = 1.0f / (float)c;
            float a[64];
            const float4* ap = (const float4*)(g_agg2 + (size_t)(g * 3 + r) * 64);
#pragma unroll
            for (int j = 0; j < 16; j++) ((float4*)a)[j] = ap[j];
            const float* wr = s_w + r * 4096;
#pragma unroll 4
            for (int k = 0; k < 64; k++) {
                float av = a[k] * inv;
                u64 hk = pack2(av, av);
                const ulonglong2* row = (const ulonglong2*)(wr + k * 64);
#pragma unroll
                for (int j = 0; j < 16; j++) {
                    ulonglong2 w = row[j];
                    m[2 * j]     = fma2(hk, w.x, m[2 * j]);
                    m[2 * j + 1] = fma2(hk, w.y, m[2 * j + 1]);
                }
            }
        }
    }
    float o[64];
#pragma unroll
    for (int j = 0; j < 32; j++) {
        float a, b; unpack2(m[j], a, b);
        o[2 * j] = fmaxf(a, 0.f); o[2 * j + 1] = fmaxf(b, 0.f);
    }
    float res[10];
#pragma unroll
    for (int c = 0; c < 10; c++) res[c] = __ldg(&cb[c]);
#pragma unroll 8
    for (int k = 0; k < 64; k++) {
        float hk = o[k];
#pragma unroll
        for (int c = 0; c < 10; c++) res[c] = fmaf(hk, __ldg(&cls[k * 10 + c]), res[c]);
    }
#pragma unroll
    for (int c = 0; c < 10; c++) out[(size_t)g * 10 + c] = res[c];
}

// ---- PDL launch helper: overlap launch/prologue with predecessor ----
static void launch_pdl(const void* fn, int grid, int block, void** args) {
    cudaLaunchConfig_t cfg = {};
    cfg.gridDim = dim3(grid, 1, 1);
    cfg.blockDim = dim3(block, 1, 1);
    cudaLaunchAttribute attr[1];
    attr[0].id = cudaLaunchAttributeProgrammaticStreamSerialization;
    attr[0].val.programmaticStreamSerializationAllowed = 1;
    cfg.attrs = attr;
    cfg.numAttrs = 1;
    cudaLaunchKernelExC(&cfg, fn, args);
}

extern "C" void kernel_launch(void* const* d_in, const int* in_sizes, int n_in,
                              void* d_out, int out_size)
{
    const int*   x      = (const int*)d_in[0];
    const int*   ei     = (const int*)d_in[1];
    const int*   et     = (const int*)d_in[2];
    const int*   ptr    = (const int*)d_in[3];
    const float* se     = (const float*)d_in[4];
    const float* ce     = (const float*)d_in[5];
    const float* pw     = (const float*)d_in[6];
    const float* pb     = (const float*)d_in[7];
    const float* w1rel  = (const float*)d_in[8];
    const float* w1root = (const float*)d_in[9];
    const float* b1     = (const float*)d_in[10];
    const float* w2rel  = (const float*)d_in[11];
    const float* w2root = (const float*)d_in[12];
    const float* b2     = (const float*)d_in[13];
    const float* cw     = (const float*)d_in[14];
    const float* cb     = (const float*)d_in[15];
    float* out = (float*)d_out;

    int n = in_sizes[0] / 2;       // nodes
    int E = in_sizes[1] / 2;       // edges
    int G = in_sizes[3] - 1;       // graphs
    int nw = (n + 31) / 32;

    k_init<<<256, 256>>>(ptr, n, G);

    {   // passA
        void* a[] = {(void*)&ei, (void*)&et, (void*)&ptr, (void*)&E, (void*)&G};
        launch_pdl((const void*)k_passA, (E + 2047) / 2048, 256, a);
    }
    {   // compact
        void* a[] = {(void*)&nw};
        launch_pdl((const void*)k_compact, (nw + 255) / 256, 256, a);
    }
    {   // fused passB + layer-1 aggregation
        void* a[] = {(void*)&ei, (void*)&et, (void*)&x, (void*)&se, (void*)&ce,
                     (void*)&pw, (void*)&pb, (void*)&E};
        launch_pdl((const void*)k_passBh1, (E + 2047) / 2048, 256, a);
    }
    {   // h1
        void* a[] = {(void*)&x, (void*)&se, (void*)&ce, (void*)&pw, (void*)&pb,
                     (void*)&w1rel, (void*)&w1root, (void*)&b1};
        launch_pdl((const void*)k_h1, 296, 256, a);
    }
    {   // h2agg
        launch_pdl((const void*)k_h2agg, 296, 256, nullptr);
    }
    {   // out
        void* a[] = {(void*)&ptr, (void*)&w2root, (void*)&b2, (void*)&w2rel,
                     (void*)&cw, (void*)&cb, (void*)&out, (void*)&G};
        launch_pdl((const void*)k_out, (G + 255) / 256, 256, a);
    }
}

// round 16
// speedup vs baseline: 1.0997x; 1.0192x over previous
#include <cuda_runtime.h>

typedef unsigned long long u64;

#define NMAX 500000
#define EMAX 1000000
#define GMAX 5000
#define NWORDS ((NMAX + 31) / 32)
#define NTB 148            // tail kernel blocks (<= SM count, all co-resident)

// ---- persistent scratch ----
__device__ unsigned g_tbits[NWORDS];             // target-node bitmask (fallback path)
__device__ unsigned g_sbits[NWORDS];             // S1 bitmask (targets + L2 srcs)
__device__ int    g_idx1[NMAX];                  // node -> compact S1 index
__device__ int    g_s1nodes[NMAX];               // compact S1 index -> node
__device__ int    g_cnt1[3 * NMAX];              // [p*3+r] in-edge count (layer1)
__device__ int    g_cnt2[3 * GMAX];              // [g*3+r] in-edge count at targets
__device__ float  g_agg1[(size_t)NMAX * 96];     // [(p*3+r)*32] raw h0 sums
__device__ float  g_agg2[GMAX * 192];            // [(g*3+r)*64] raw h1 sums
__device__ float4 g_h1[(size_t)NMAX * 16];       // [p][64] relu'd layer-1 output
__device__ int2   g_L2[EMAX];                    // (src, g*3+r)
__device__ int    g_ctr[8];                      // 0=L2 count, 1=S1 count
__device__ int    g_bad_flag;                    // ptr non-uniform? sticky, deterministic
__device__ unsigned g_bcount[4];                 // tail barrier arrive counters (self-reset)
__device__ unsigned g_bgen[4];                   // tail barrier generations (monotonic)

// ---- packed f32x2 helpers ----
__device__ __forceinline__ u64 pack2(float x, float y) {
    u64 d;
    asm("mov.b64 %0, {%1, %2};" : "=l"(d) : "r"(__float_as_uint(x)), "r"(__float_as_uint(y)));
    return d;
}
__device__ __forceinline__ void unpack2(u64 v, float& x, float& y) {
    unsigned a, b;
    asm("mov.b64 {%0, %1}, %2;" : "=r"(a), "=r"(b) : "l"(v));
    x = __uint_as_float(a); y = __uint_as_float(b);
}
__device__ __forceinline__ u64 fma2(u64 a, u64 b, u64 c) {
    u64 d;
    asm("fma.rn.f32x2 %0, %1, %2, %3;" : "=l"(d) : "l"(a), "l"(b), "l"(c));
    return d;
}
__device__ __forceinline__ void red4(float* p, float a, float b, float c, float d) {
    asm volatile("red.global.add.v4.f32 [%0], {%1, %2, %3, %4};"
                 :: "l"(p), "f"(a), "f"(b), "f"(c), "f"(d) : "memory");
}
__device__ __forceinline__ void red1(float* p, float a) {
    asm volatile("red.global.add.f32 [%0], %1;" :: "l"(p), "f"(a) : "memory");
}

// ---- replay-safe grid barrier (count self-resets, gen monotonic) ----
__device__ __forceinline__ void gbar(int id) {
    __threadfence();
    __syncthreads();
    if (threadIdx.x == 0) {
        volatile unsigned* genp = (volatile unsigned*)&g_bgen[id];
        unsigned gen = *genp;
        unsigned old = atomicAdd(&g_bcount[id], 1u);
        if (old == NTB - 1) {
            g_bcount[id] = 0;
            __threadfence();
            atomicAdd(&g_bgen[id], 1u);
        } else {
            while (*genp == gen) __nanosleep(32);
        }
    }
    __syncthreads();
}

// ---- count-based warp claim: thread claims c slots, ONE atomic per warp ----
__device__ __forceinline__ int warp_claim_n(int* ctr, int c) {
    int lane = threadIdx.x & 31;
    int inc = c;
#pragma unroll
    for (int off = 1; off < 32; off <<= 1) {
        int v = __shfl_up_sync(0xffffffffu, inc, off);
        if (lane >= off) inc += v;
    }
    int tot = __shfl_sync(0xffffffffu, inc, 31);
    int base = 0;
    if (lane == 31 && tot > 0) base = atomicAdd(ctr, tot);
    base = __shfl_sync(0xffffffffu, base, 31);
    return base + inc - c;
}

// ---- on-the-fly h0 (thread-serial form; used by tail phase 1) ----
__device__ __forceinline__ void compute_h0(
    int node, const int* __restrict__ x,
    const float* s_se, const float* s_ce,
    const float* s_pw, const float* s_pb, float* h)
{
    int x0 = __ldg(&x[2 * node]);
    int x1 = __ldg(&x[2 * node + 1]);
    float v[16];
    const float4* sp = (const float4*)(s_se + x0 * 8);
    const float4* cp = (const float4*)(s_ce + x1 * 8);
    ((float4*)v)[0] = sp[0]; ((float4*)v)[1] = sp[1];
    ((float4*)v)[2] = cp[0]; ((float4*)v)[3] = cp[1];

    u64 m[16];
#pragma unroll
    for (int j = 0; j < 16; j++) m[j] = pack2(s_pb[2 * j], s_pb[2 * j + 1]);
#pragma unroll
    for (int k = 0; k < 16; k++) {
        u64 hk = pack2(v[k], v[k]);
        const ulonglong2* row = (const ulonglong2*)(s_pw + k * 32);
#pragma unroll
        for (int j = 0; j < 8; j++) {
            ulonglong2 w = row[j];
            m[2 * j]     = fma2(hk, w.x, m[2 * j]);
            m[2 * j + 1] = fma2(hk, w.y, m[2 * j + 1]);
        }
    }
#pragma unroll
    for (int j = 0; j < 16; j++) {
        float a, b; unpack2(m[j], a, b);
        h[2 * j] = fmaxf(a, 0.f); h[2 * j + 1] = fmaxf(b, 0.f);
    }
}

// ---- init: uniformity probe; target bitmask; clear agg2/cnt2/ctr ----
__global__ __launch_bounds__(256) void k_init(const int* __restrict__ ptr, int n, int G) {
    int gid = blockIdx.x * 256 + threadIdx.x;
    int total = gridDim.x * 256;
    int nw = (n + 31) / 32;

    int s0 = __ldg(&ptr[1]) - __ldg(&ptr[0]);
    for (int g = gid; g < G; g += total) {
        bool bad = (__ldg(&ptr[g + 1]) - __ldg(&ptr[g]) != s0);
        if (g == 0) bad |= (__ldg(&ptr[0]) != 0) | (s0 <= 0);
        if (bad) atomicOr(&g_bad_flag, 1);
    }

    for (int w = gid; w < nw; w += total) {
        int base = w * 32;
        int lo = 0, hi = G;
        while (lo < hi) {
            int mid = (lo + hi) >> 1;
            if (__ldg(&ptr[mid + 1]) < base + 1) lo = mid + 1; else hi = mid;
        }
        unsigned bits = 0;
        int g = lo;
        while (g < G) {
            int t = __ldg(&ptr[g + 1]) - 1;
            if (t >= base + 32) break;
            if (t >= base && t < n) bits |= 1u << (t - base);
            g++;
        }
        g_tbits[w] = bits;
        g_sbits[w] = bits;
    }
    int m2 = 3 * G * 64 / 4;
    float4 z = make_float4(0.f, 0.f, 0.f, 0.f);
    for (int j = gid; j < m2; j += total) ((float4*)g_agg2)[j] = z;
    for (int j = gid; j < 3 * G; j += total) g_cnt2[j] = 0;
    if (gid < 8) g_ctr[gid] = 0;
}

// ---- pass A: 8 edges/thread; arithmetic fast path; loads pre-sync ----
__global__ __launch_bounds__(256) void k_passA(
    const int* __restrict__ ei, const int* __restrict__ et,
    const int* __restrict__ ptr, int E, int G)
{
    unsigned s = (unsigned)(__ldg(&ptr[1]) - __ldg(&ptr[0]));
    int t8 = (blockIdx.x * 256 + threadIdx.x) * 8;

    int d[8]; bool ahit[8]; int arank[8]; bool valid[8];
    if (t8 + 7 < E) {
        int4 v0 = *(const int4*)(ei + E + t8);
        int4 v1 = *(const int4*)(ei + E + t8 + 4);
        d[0] = v0.x; d[1] = v0.y; d[2] = v0.z; d[3] = v0.w;
        d[4] = v1.x; d[5] = v1.y; d[6] = v1.z; d[7] = v1.w;
#pragma unroll
        for (int j = 0; j < 8; j++) valid[j] = true;
    } else {
#pragma unroll
        for (int j = 0; j < 8; j++) {
            valid[j] = (t8 + j < E);
            d[j] = valid[j] ? __ldg(&ei[E + t8 + j]) : 0;
        }
    }
#pragma unroll
    for (int j = 0; j < 8; j++) {
        unsigned q = (unsigned)d[j] / s;
        ahit[j] = valid[j] && ((unsigned)d[j] - q * s == s - 1);
        arank[j] = (int)q;
    }

    cudaGridDependencySynchronize();
    bool uni = (g_bad_flag == 0);

    bool hit[8];
    if (uni) {
#pragma unroll
        for (int j = 0; j < 8; j++) hit[j] = ahit[j];
    } else {
#pragma unroll
        for (int j = 0; j < 8; j++)
            hit[j] = valid[j] && ((__ldg(&g_tbits[d[j] >> 5]) >> (d[j] & 31)) & 1);
    }
    int c = 0;
#pragma unroll
    for (int j = 0; j < 8; j++) c += (int)hit[j];
    int pos = warp_claim_n(&g_ctr[0], c);
#pragma unroll
    for (int j = 0; j < 8; j++) {
        if (hit[j]) {
            int e = t8 + j;
            int rank;
            if (uni) rank = arank[j];
            else {
                int dj = d[j];
                int lo = 0, hi = G - 1;
                while (lo < hi) {
                    int mid = (lo + hi + 1) >> 1;
                    if (__ldg(&ptr[mid]) <= dj) lo = mid; else hi = mid - 1;
                }
                rank = lo;
            }
            int r = __ldg(&et[e]);
            int sE = __ldg(&ei[e]);
            int code = rank * 3 + r;
            g_L2[pos++] = make_int2(sE, code);
            atomicAdd(&g_cnt2[code], 1);
            atomicOr(&g_sbits[sE >> 5], 1u << (sE & 31));
        }
    }
}

// ---- compact S1 from bitmask (1 word / thread, warp-scan claim) ----
__global__ __launch_bounds__(256) void k_compact(int nw) {
    int w = blockIdx.x * 256 + threadIdx.x;
    cudaGridDependencySynchronize();
    unsigned bits = (w < nw) ? g_sbits[w] : 0u;
    int p = warp_claim_n(&g_ctr[1], __popc(bits));
    float4 z = make_float4(0.f, 0.f, 0.f, 0.f);
    while (bits) {
        int b = __ffs(bits) - 1;
        bits &= bits - 1;
        int node = w * 32 + b;
        g_idx1[node] = p;
        g_s1nodes[p] = node;
        g_cnt1[p * 3] = 0; g_cnt1[p * 3 + 1] = 0; g_cnt1[p * 3 + 2] = 0;
        float4* a = (float4*)(g_agg1 + (size_t)p * 96);
#pragma unroll
        for (int k = 0; k < 24; k++) a[k] = z;
        p++;
    }
}

// ---- FUSED pass B + layer-1 aggregation ----
__global__ __launch_bounds__(256) void k_passBh1(
    const int* __restrict__ ei, const int* __restrict__ et,
    const int* __restrict__ x,
    const float* __restrict__ se, const float* __restrict__ ce,
    const float* __restrict__ pw, const float* __restrict__ pb, int E)
{
    __shared__ float s_se[128], s_ce[128];
    __shared__ int s_src[2048];
    __shared__ int s_code[2048];
    __shared__ int s_nhits;
    int t = threadIdx.x;
    int lane = t & 31;
    int wid = t >> 5;

    if (t < 128) { s_se[t] = se[t]; s_ce[t] = ce[t]; }
    if (t == 0) s_nhits = 0;
    float r_pw[16];
#pragma unroll
    for (int k = 0; k < 16; k++) r_pw[k] = __ldg(&pw[k * 32 + lane]);
    float r_pb = __ldg(&pb[lane]);

    int t8 = (blockIdx.x * 256 + t) * 8;
    int d[8];
    int4 v0, v1; bool full = (t8 + 7 < E);
    if (full) {
        v0 = *(const int4*)(ei + E + t8);
        v1 = *(const int4*)(ei + E + t8 + 4);
    }
    __syncthreads();

    cudaGridDependencySynchronize();

    bool hit[8];
    if (full) {
        d[0] = v0.x; d[1] = v0.y; d[2] = v0.z; d[3] = v0.w;
        d[4] = v1.x; d[5] = v1.y; d[6] = v1.z; d[7] = v1.w;
#pragma unroll
        for (int j = 0; j < 8; j++)
            hit[j] = (__ldg(&g_sbits[d[j] >> 5]) >> (d[j] & 31)) & 1;
    } else {
#pragma unroll
        for (int j = 0; j < 8; j++) {
            hit[j] = false;
            if (t8 + j < E) {
                d[j] = __ldg(&ei[E + t8 + j]);
                hit[j] = (__ldg(&g_sbits[d[j] >> 5]) >> (d[j] & 31)) & 1;
            }
        }
    }
#pragma unroll
    for (int j = 0; j < 8; j++) {
        if (hit[j]) {
            int e = t8 + j;
            int p = __ldg(&g_idx1[d[j]]);
            int r = __ldg(&et[e]);
            int s = __ldg(&ei[e]);
            int code = p * 3 + r;
            atomicAdd(&g_cnt1[code], 1);
            int slot = atomicAdd(&s_nhits, 1);
            s_src[slot] = s;
            s_code[slot] = code;
        }
    }
    __syncthreads();

    int n = s_nhits;
    for (int h = wid; h < n; h += 8) {
        int src = s_src[h];
        int code = s_code[h];
        int x0 = __ldg(&x[2 * src]);
        int x1 = __ldg(&x[2 * src + 1]);
        float acc = r_pb;
        const float* sev = s_se + x0 * 8;
        const float* cev = s_ce + x1 * 8;
#pragma unroll
        for (int k = 0; k < 8; k++) acc = fmaf(sev[k], r_pw[k], acc);
#pragma unroll
        for (int k = 0; k < 8; k++) acc = fmaf(cev[k], r_pw[8 + k], acc);
        acc = fmaxf(acc, 0.f);
        red1(g_agg1 + (size_t)code * 32 + lane, acc);
    }
}

// ---- FUSED tail: h1 -> (gbar) -> h2agg -> (gbar) -> out ----
__global__ __launch_bounds__(256, 1) void k_tail(
    const int* __restrict__ x,
    const float* __restrict__ se, const float* __restrict__ ce,
    const float* __restrict__ pw, const float* __restrict__ pb,
    const float* __restrict__ w1rel, const float* __restrict__ w1root,
    const float* __restrict__ b1,
    const int* __restrict__ ptr, const float* __restrict__ w2root,
    const float* __restrict__ b2, const float* __restrict__ w2rel,
    const float* __restrict__ cls, const float* __restrict__ cb,
    float* __restrict__ out, int G)
{
    __shared__ __align__(16) float sm[12288];   // 48KB, repurposed per phase
    float* s_se   = sm;          // 128
    float* s_ce   = sm + 128;    // 128
    float* s_pw   = sm + 256;    // 512
    float* s_pb   = sm + 768;    // 32
    float* s_b1   = sm + 800;    // 64
    float* s_root = sm + 864;    // 2048
    float* s_rel  = sm + 2912;   // 6144 (ends 9056)

    int t = threadIdx.x;
    int gid = blockIdx.x * 256 + t;
    int total = NTB * 256;

    // stage phase-1 weights (harness inputs) — overlaps predecessor via PDL
    if (t < 128) { s_se[t] = se[t]; s_ce[t] = ce[t]; }
    for (int j = t; j < 512;  j += 256) s_pw[j] = pw[j];
    for (int j = t; j < 2048; j += 256) s_root[j] = w1root[j];
    for (int j = t; j < 6144; j += 256) s_rel[j] = w1rel[j];
    if (t < 32) s_pb[t] = pb[t];
    if (t < 64) s_b1[t] = b1[t];
    cudaGridDependencySynchronize();
    __syncthreads();

    // ---- phase 1: layer-1 transform at S1 nodes ----
    {
        int cnt = g_ctr[1];
        for (int p = gid; p < cnt; p += total) {
            int node = g_s1nodes[p];
            float h0[32];
            compute_h0(node, x, s_se, s_ce, s_pw, s_pb, h0);

            u64 m[32];
#pragma unroll
            for (int j = 0; j < 32; j++) m[j] = pack2(s_b1[2 * j], s_b1[2 * j + 1]);
#pragma unroll 4
            for (int k = 0; k < 32; k++) {
                u64 hk = pack2(h0[k], h0[k]);
                const ulonglong2* row = (const ulonglong2*)(s_root + k * 64);
#pragma unroll
                for (int j = 0; j < 16; j++) {
                    ulonglong2 w = row[j];
                    m[2 * j]     = fma2(hk, w.x, m[2 * j]);
                    m[2 * j + 1] = fma2(hk, w.y, m[2 * j + 1]);
                }
            }
            for (int r = 0; r < 3; r++) {
                int c = g_cnt1[p * 3 + r];
                if (c > 0) {
                    float inv = 1.0f / (float)c;
                    float a[32];
                    const float4* ap = (const float4*)(g_agg1 + (size_t)(p * 3 + r) * 32);
#pragma unroll
                    for (int j = 0; j < 8; j++) ((float4*)a)[j] = ap[j];
                    const float* wr = s_rel + r * 2048;
#pragma unroll 4
                    for (int k = 0; k < 32; k++) {
                        float av = a[k] * inv;
                        u64 hk = pack2(av, av);
                        const ulonglong2* row = (const ulonglong2*)(wr + k * 64);
#pragma unroll
                        for (int j = 0; j < 16; j++) {
                            ulonglong2 w = row[j];
                            m[2 * j]     = fma2(hk, w.x, m[2 * j]);
                            m[2 * j + 1] = fma2(hk, w.y, m[2 * j + 1]);
                        }
                    }
                }
            }
            float o[64];
#pragma unroll
            for (int j = 0; j < 32; j++) unpack2(m[j], o[2 * j], o[2 * j + 1]);
            float4* hp = (float4*)(g_h1 + (size_t)p * 16);
#pragma unroll
            for (int j = 0; j < 16; j++) {
                float4 w = ((float4*)o)[j];
                w.x = fmaxf(w.x, 0.f); w.y = fmaxf(w.y, 0.f);
                w.z = fmaxf(w.z, 0.f); w.w = fmaxf(w.w, 0.f);
                hp[j] = w;
            }
        }
    }
    gbar(0);

    // ---- phase 2: layer-2 aggregation; stage w2rel into sm concurrently ----
    for (int j = t; j < 12288; j += 256) sm[j] = w2rel[j];
    {
        int cnt = g_ctr[0];
        for (int idx = gid; idx < cnt; idx += total) {
            int2 e = g_L2[idx];
            int p = __ldg(&g_idx1[e.x]);
            const float4* hp = (const float4*)(g_h1 + (size_t)p * 16);
            float* dp = g_agg2 + (size_t)e.y * 64;
#pragma unroll
            for (int j = 0; j < 16; j++) {
                float4 w = hp[j];
                red4(dp + 4 * j, w.x, w.y, w.z, w.w);
            }
        }
    }
    gbar(1);

    // ---- phase 3: final transform + classifier ----
    if (gid < G) {
        int g = gid;
        int tgt = __ldg(&ptr[g + 1]) - 1;
        int p = __ldg(&g_idx1[tgt]);

        u64 m[32];
#pragma unroll
        for (int j = 0; j < 32; j++) m[j] = pack2(__ldg(&b2[2 * j]), __ldg(&b2[2 * j + 1]));

        {   // root term: h1[tgt] @ w2_root (rows via warp-broadcast LDG)
            float h[64];
            const float4* hp = (const float4*)(g_h1 + (size_t)p * 16);
#pragma unroll
            for (int j = 0; j < 16; j++) ((float4*)h)[j] = hp[j];
#pragma unroll 4
            for (int k = 0; k < 64; k++) {
                u64 hk = pack2(h[k], h[k]);
                const ulonglong2* row = (const ulonglong2*)(w2root + k * 64);
#pragma unroll
                for (int j = 0; j < 16; j++) {
                    ulonglong2 w = __ldg(&row[j]);
                    m[2 * j]     = fma2(hk, w.x, m[2 * j]);
                    m[2 * j + 1] = fma2(hk, w.y, m[2 * j + 1]);
                }
            }
        }
        for (int r = 0; r < 3; r++) {
            int c = g_cnt2[g * 3 + r];
            if (c > 0) {
                float inv = 1.0f / (float)c;
                float a[64];
                const float4* ap = (const float4*)(g_agg2 + (size_t)(g * 3 + r) * 64);
#pragma unroll
                for (int j = 0; j < 16; j++) ((float4*)a)[j] = ap[j];
                const float* wr = sm + r * 4096;
#pragma unroll 4
                for (int k = 0; k < 64; k++) {
                    float av = a[k] * inv;
                    u64 hk = pack2(av, av);
                    const ulonglong2* row = (const ulonglong2*)(wr + k * 64);
#pragma unroll
                    for (int j = 0; j < 16; j++) {
                        ulonglong2 w = row[j];
                        m[2 * j]     = fma2(hk, w.x, m[2 * j]);
                        m[2 * j + 1] = fma2(hk, w.y, m[2 * j + 1]);
                    }
                }
            }
        }
        float o[64];
#pragma unroll
        for (int j = 0; j < 32; j++) {
            float a, b; unpack2(m[j], a, b);
            o[2 * j] = fmaxf(a, 0.f); o[2 * j + 1] = fmaxf(b, 0.f);
        }
        float res[10];
#pragma unroll
        for (int c = 0; c < 10; c++) res[c] = __ldg(&cb[c]);
#pragma unroll 8
        for (int k = 0; k < 64; k++) {
            float hk = o[k];
#pragma unroll
            for (int c = 0; c < 10; c++) res[c] = fmaf(hk, __ldg(&cls[k * 10 + c]), res[c]);
        }
#pragma unroll
        for (int c = 0; c < 10; c++) out[(size_t)g * 10 + c] = res[c];
    }
}

// ---- PDL launch helper: overlap launch/prologue with predecessor ----
static void launch_pdl(const void* fn, int grid, int block, void** args) {
    cudaLaunchConfig_t cfg = {};
    cfg.gridDim = dim3(grid, 1, 1);
    cfg.blockDim = dim3(block, 1, 1);
    cudaLaunchAttribute attr[1];
    attr[0].id = cudaLaunchAttributeProgrammaticStreamSerialization;
    attr[0].val.programmaticStreamSerializationAllowed = 1;
    cfg.attrs = attr;
    cfg.numAttrs = 1;
    cudaLaunchKernelExC(&cfg, fn, args);
}

extern "C" void kernel_launch(void* const* d_in, const int* in_sizes, int n_in,
                              void* d_out, int out_size)
{
    const int*   x      = (const int*)d_in[0];
    const int*   ei     = (const int*)d_in[1];
    const int*   et     = (const int*)d_in[2];
    const int*   ptr    = (const int*)d_in[3];
    const float* se     = (const float*)d_in[4];
    const float* ce     = (const float*)d_in[5];
    const float* pw     = (const float*)d_in[6];
    const float* pb     = (const float*)d_in[7];
    const float* w1rel  = (const float*)d_in[8];
    const float* w1root = (const float*)d_in[9];
    const float* b1     = (const float*)d_in[10];
    const float* w2rel  = (const float*)d_in[11];
    const float* w2root = (const float*)d_in[12];
    const float* b2     = (const float*)d_in[13];
    const float* cw     = (const float*)d_in[14];
    const float* cb     = (const float*)d_in[15];
    float* out = (float*)d_out;

    int n = in_sizes[0] / 2;       // nodes
    int E = in_sizes[1] / 2;       // edges
    int G = in_sizes[3] - 1;       // graphs
    int nw = (n + 31) / 32;

    k_init<<<256, 256>>>(ptr, n, G);

    {   // passA
        void* a[] = {(void*)&ei, (void*)&et, (void*)&ptr, (void*)&E, (void*)&G};
        launch_pdl((const void*)k_passA, (E + 2047) / 2048, 256, a);
    }
    {   // compact
        void* a[] = {(void*)&nw};
        launch_pdl((const void*)k_compact, (nw + 255) / 256, 256, a);
    }
    {   // fused passB + layer-1 aggregation
        void* a[] = {(void*)&ei, (void*)&et, (void*)&x, (void*)&se, (void*)&ce,
                     (void*)&pw, (void*)&pb, (void*)&E};
        launch_pdl((const void*)k_passBh1, (E + 2047) / 2048, 256, a);
    }
    {   // fused tail: h1 + h2agg + out
        void* a[] = {(void*)&x, (void*)&se, (void*)&ce, (void*)&pw, (void*)&pb,
                     (void*)&w1rel, (void*)&w1root, (void*)&b1,
                     (void*)&ptr, (void*)&w2root, (void*)&b2, (void*)&w2rel,
                     (void*)&cw, (void*)&cb, (void*)&out, (void*)&G};
        launch_pdl((const void*)k_tail, NTB, 256, a);
    }
}